// round 5
// baseline (speedup 1.0000x reference)
#include <cuda_runtime.h>
#include <cstdint>

#define N 4096
#define H 64
#define NLAYER 3
#define MAXD 128
#define NEG 0.2f
#define EPS 1e-5f
#define FIN_BLOCKS (N / 8)   // 512

// ---------------- scratch ----------------
__device__ float g_x[N * H];
__device__ float g_h[N * H];
__device__ float g_hw[N * H];
__device__ float g_ssrc[N];
__device__ float g_sdst[N];
__device__ int   g_deg[N];
__device__ int   g_cols[N * MAXD];
__device__ float g_part[FIN_BLOCKS * H];

// ---------------- k_embed: fold MLP per-block + node features + degree init ----------------
__global__ void k_embed(const int* __restrict__ ts,
                        const float* __restrict__ arr, const float* __restrict__ dep,
                        const float* __restrict__ hard,
                        const float* __restrict__ w1, const float* __restrict__ b1,
                        const float* __restrict__ w2, const float* __restrict__ b2) {
    __shared__ float sc1[64], sc2[64], sc3[64];
    int tid = threadIdx.x;
    if (tid < 64) {
        float c1 = 0.f, c2 = 0.f, c3 = 0.f;
        #pragma unroll 8
        for (int k = 0; k < 64; k++) {
            float w = w2[k * 64 + tid];
            c1 += w1[k] * w;
            c2 += w1[64 + k] * w;
            c3 += b1[k] * w;
        }
        sc1[tid] = c1; sc2[tid] = c2; sc3[tid] = c3 + b2[tid];
    }
    int gi = blockIdx.x * 256 + tid;
    if (gi < N) { g_deg[gi] = 1; g_cols[gi * MAXD] = gi; }
    __syncthreads();

    int b = *ts;
    float t = (b > -100000 && b < 100000) ? (float)b : __int_as_float(b);
    int base = blockIdx.x * 4096;
    #pragma unroll
    for (int it = 0; it < 16; it++) {
        int idx = base + it * 256 + tid;
        int i = idx >> 6, c = idx & 63;
        float p = (t - arr[i]) / (dep[i] - arr[i]);
        float v = p * sc1[c] + hard[i] * sc2[c] + sc3[c];
        g_x[idx] = v;
        g_h[idx] = v;
    }
}

// ---------------- k_edges: build in-neighbor lists (float4 streaming, 128 slices) ----------------
__global__ void k_edges(const float* __restrict__ adj) {
    int gid = blockIdx.x * blockDim.x + threadIdx.x;   // 131072 threads
    int i4 = gid & (N / 4 - 1);
    int s = gid >> 10;                                  // 0..127
    const int JS = 32;
    int j0 = s * JS;
    const float4* p = (const float4*)adj + (size_t)j0 * (N / 4) + i4;
    int i = i4 * 4;
    #pragma unroll 4
    for (int jj = 0; jj < JS; jj++) {
        float4 v = __ldcs(p);
        p += N / 4;
        int j = j0 + jj;
        if (v.x != 0.f && j != i) {
            int sl = atomicAdd(&g_deg[i], 1);
            if (sl < MAXD) g_cols[i * MAXD + sl] = j;
        }
        if (v.y != 0.f && j != i + 1) {
            int sl = atomicAdd(&g_deg[i + 1], 1);
            if (sl < MAXD) g_cols[(i + 1) * MAXD + sl] = j;
        }
        if (v.z != 0.f && j != i + 2) {
            int sl = atomicAdd(&g_deg[i + 2], 1);
            if (sl < MAXD) g_cols[(i + 2) * MAXD + sl] = j;
        }
        if (v.w != 0.f && j != i + 3) {
            int sl = atomicAdd(&g_deg[i + 3], 1);
            if (sl < MAXD) g_cols[(i + 3) * MAXD + sl] = j;
        }
    }
}

// ---------------- k_gemm: one warp per row, W in smem, h via shfl, fused scores ----------------
__global__ void k_gemm(const float* __restrict__ W,
                       const float* __restrict__ asrc, const float* __restrict__ adst) {
    __shared__ float sW[64 * 64];       // 16KB
    int tid = threadIdx.x;
    const float4* Wv = (const float4*)W;
    float4* sWv = (float4*)sW;
    #pragma unroll 4
    for (int e = tid; e < 1024; e += 256) sWv[e] = Wv[e];
    __syncthreads();

    int w = tid >> 5, lane = tid & 31;
    int row = blockIdx.x * 8 + w;
    float h0 = g_h[row * 64 + lane];
    float h1 = g_h[row * 64 + 32 + lane];

    float a0 = 0.f, a1 = 0.f;
    const int c2 = lane * 2;
    #pragma unroll
    for (int k = 0; k < 32; k++) {
        float hk = __shfl_sync(0xffffffffu, h0, k);
        float2 wv = *(const float2*)&sW[k * 64 + c2];
        a0 += hk * wv.x; a1 += hk * wv.y;
    }
    #pragma unroll
    for (int k = 0; k < 32; k++) {
        float hk = __shfl_sync(0xffffffffu, h1, k);
        float2 wv = *(const float2*)&sW[(k + 32) * 64 + c2];
        a0 += hk * wv.x; a1 += hk * wv.y;
    }
    *(float2*)&g_hw[row * 64 + c2] = make_float2(a0, a1);

    float2 as = ((const float2*)asrc)[lane];
    float2 ad = ((const float2*)adst)[lane];
    float s = a0 * as.x + a1 * as.y;
    float d = a0 * ad.x + a1 * ad.y;
    #pragma unroll
    for (int o = 16; o; o >>= 1) {
        s += __shfl_xor_sync(0xffffffffu, s, o);
        d += __shfl_xor_sync(0xffffffffu, d, o);
    }
    if (lane == 0) { g_ssrc[row] = s; g_sdst[row] = d; }
}

// ---------------- k_attn: warp per row, two-phase (weights then ILP gather) ----------------
__global__ void k_attn(const float* __restrict__ bias, int do_relu) {
    __shared__ int   sj[8][MAXD];
    __shared__ float swt[8][MAXD];
    int tid = threadIdx.x;
    int w = tid >> 5, lane = tid & 31;
    int i = blockIdx.x * 8 + w;

    int d = g_deg[i]; if (d > MAXD) d = MAXD;
    int base = i * MAXD;
    float sd = g_sdst[i];

    // ---- phase A: lane-parallel logits ----
    float ev[4]; int jv[4];
    float mx = -1e30f;
    #pragma unroll
    for (int u = 0; u < 4; u++) {
        int t = lane + u * 32;
        if (t < d) {
            int j = g_cols[base + t];
            float e = g_ssrc[j] + sd;
            e = e > 0.f ? e : NEG * e;
            jv[u] = j; ev[u] = e;
            mx = fmaxf(mx, e);
        } else { ev[u] = -1e30f; jv[u] = 0; }
    }
    #pragma unroll
    for (int o = 16; o; o >>= 1) mx = fmaxf(mx, __shfl_xor_sync(0xffffffffu, mx, o));

    float den = 0.f;
    #pragma unroll
    for (int u = 0; u < 4; u++) {
        int t = lane + u * 32;
        if (t < d) {
            float wv = __expf(ev[u] - mx);
            den += wv;
            sj[w][t] = jv[u];
            swt[w][t] = wv;
        }
    }
    #pragma unroll
    for (int o = 16; o; o >>= 1) den += __shfl_xor_sync(0xffffffffu, den, o);
    __syncwarp();

    // ---- phase B: unroll-4 gather with independent accumulators ----
    const int c2 = lane * 2;
    float2 A0 = make_float2(0.f, 0.f), A1 = make_float2(0.f, 0.f);
    float2 A2 = make_float2(0.f, 0.f), A3 = make_float2(0.f, 0.f);
    int t = 0;
    for (; t + 4 <= d; t += 4) {
        int j0 = sj[w][t],     j1 = sj[w][t + 1];
        int j2 = sj[w][t + 2], j3 = sj[w][t + 3];
        float w0 = swt[w][t],     w1 = swt[w][t + 1];
        float w2 = swt[w][t + 2], w3 = swt[w][t + 3];
        float2 h0 = *(const float2*)&g_hw[j0 * 64 + c2];
        float2 h1 = *(const float2*)&g_hw[j1 * 64 + c2];
        float2 h2 = *(const float2*)&g_hw[j2 * 64 + c2];
        float2 h3 = *(const float2*)&g_hw[j3 * 64 + c2];
        A0.x += w0 * h0.x; A0.y += w0 * h0.y;
        A1.x += w1 * h1.x; A1.y += w1 * h1.y;
        A2.x += w2 * h2.x; A2.y += w2 * h2.y;
        A3.x += w3 * h3.x; A3.y += w3 * h3.y;
    }
    for (; t < d; t++) {
        int j0 = sj[w][t];
        float w0 = swt[w][t];
        float2 h0 = *(const float2*)&g_hw[j0 * 64 + c2];
        A0.x += w0 * h0.x; A0.y += w0 * h0.y;
    }
    float inv = 1.0f / den;
    float o0 = (A0.x + A1.x + A2.x + A3.x) * inv;
    float o1 = (A0.y + A1.y + A2.y + A3.y) * inv;
    float2 bb = ((const float2*)bias)[lane];
    o0 += bb.x; o1 += bb.y;
    if (do_relu) { o0 = fmaxf(o0, 0.f); o1 = fmaxf(o1, 0.f); }
    *(float2*)&g_h[i * 64 + c2] = make_float2(o0, o1);
}

// ---------------- k_final1: residual + layernorm + per-block column partials ----------------
__global__ void k_final1() {
    __shared__ float sn[8 * 64];
    int w = threadIdx.x >> 5, lane = threadIdx.x & 31;
    int i = blockIdx.x * 8 + w;
    float v0 = g_x[i * 64 + lane]      + g_h[i * 64 + lane];
    float v1 = g_x[i * 64 + 32 + lane] + g_h[i * 64 + 32 + lane];
    float s = v0 + v1;
    #pragma unroll
    for (int o = 16; o; o >>= 1) s += __shfl_xor_sync(0xffffffffu, s, o);
    float mu = s * (1.0f / 64.0f);
    float d0 = v0 - mu, d1 = v1 - mu;
    float q = d0 * d0 + d1 * d1;
    #pragma unroll
    for (int o = 16; o; o >>= 1) q += __shfl_xor_sync(0xffffffffu, q, o);
    float r = rsqrtf(q * (1.0f / 64.0f) + EPS);
    sn[w * 64 + lane]      = d0 * r;
    sn[w * 64 + 32 + lane] = d1 * r;
    __syncthreads();
    if (threadIdx.x < 64) {
        float p = 0.f;
        #pragma unroll
        for (int ww = 0; ww < 8; ww++) p += sn[ww * 64 + threadIdx.x];
        g_part[blockIdx.x * 64 + threadIdx.x] = p;
    }
}

// ---------------- k_final2: finish mean-pool, value head ----------------
__global__ void k_final2(const float* __restrict__ vw, const float* __restrict__ vb,
                         float* __restrict__ out) {
    __shared__ float sm[256];
    int c = threadIdx.x & 63, g = threadIdx.x >> 6;
    float s = 0.f;
    for (int b = g; b < FIN_BLOCKS; b += 4) s += g_part[b * 64 + c];
    sm[threadIdx.x] = s;
    __syncthreads();
    if (threadIdx.x < 64) {
        float pooled = (sm[c] + sm[64 + c] + sm[128 + c] + sm[192 + c]) * (1.0f / (float)N);
        sm[c] = pooled * vw[c];
    }
    __syncthreads();
    if (threadIdx.x < 32) {
        float t = sm[threadIdx.x] + sm[threadIdx.x + 32];
        #pragma unroll
        for (int o = 16; o; o >>= 1) t += __shfl_xor_sync(0xffffffffu, t, o);
        if (threadIdx.x == 0) {
            float r = t + vb[0];
            out[0] = r > 0.f ? r : 0.f;
        }
    }
}

// ---------------- host ----------------
extern "C" void kernel_launch(void* const* d_in, const int* in_sizes, int n_in,
                              void* d_out, int out_size) {
    const float* adj      = (const float*)d_in[0];
    const int*   ts       = (const int*)  d_in[1];
    const float* arrivals = (const float*)d_in[2];
    const float* depart   = (const float*)d_in[3];
    const float* hard     = (const float*)d_in[4];
    const float* emb_w1   = (const float*)d_in[6];
    const float* emb_b1   = (const float*)d_in[7];
    const float* emb_w2   = (const float*)d_in[8];
    const float* emb_b2   = (const float*)d_in[9];
    const float* gat_w    = (const float*)d_in[10];
    const float* gat_asrc = (const float*)d_in[11];
    const float* gat_adst = (const float*)d_in[12];
    const float* gat_b    = (const float*)d_in[13];
    const float* val_w    = (const float*)d_in[14];
    const float* val_b    = (const float*)d_in[15];

    k_embed<<<64, 256>>>(ts, arrivals, depart, hard, emb_w1, emb_b1, emb_w2, emb_b2);
    k_edges<<<512, 256>>>(adj);

    for (int l = 0; l < NLAYER; l++) {
        k_gemm<<<N / 8, 256>>>(gat_w + l * H * H, gat_asrc + l * H, gat_adst + l * H);
        k_attn<<<N / 8, 256>>>(gat_b + l * H, (l < NLAYER - 1) ? 1 : 0);
    }

    k_final1<<<FIN_BLOCKS, 256>>>();
    k_final2<<<1, 256>>>(val_w, val_b, (float*)d_out);
}

// round 6
// speedup vs baseline: 1.4708x; 1.4708x over previous
#include <cuda_runtime.h>
#include <cstdint>

#define N 4096
#define H 64
#define NLAYER 3
#define MAXD 128
#define NEG 0.2f
#define EPS 1e-5f
#define FIN_BLOCKS (N / 8)   // 512

// ---------------- scratch ----------------
__device__ float g_x[N * H];
__device__ float g_h[N * H];
__device__ float g_hw[N * H];
__device__ float g_ssrc[N];
__device__ float g_sdst[N];
__device__ int   g_deg[N];
__device__ int   g_cols[N * MAXD];
__device__ float g_part[FIN_BLOCKS * H];

// ---------------- k_embed: fold MLP per-block + node features + degree init ----------------
__global__ void k_embed(const int* __restrict__ ts,
                        const float* __restrict__ arr, const float* __restrict__ dep,
                        const float* __restrict__ hard,
                        const float* __restrict__ w1, const float* __restrict__ b1,
                        const float* __restrict__ w2, const float* __restrict__ b2) {
    __shared__ float sc1[64], sc2[64], sc3[64];
    int tid = threadIdx.x;
    if (tid < 64) {
        float c1 = 0.f, c2 = 0.f, c3 = 0.f;
        #pragma unroll 8
        for (int k = 0; k < 64; k++) {
            float w = w2[k * 64 + tid];
            c1 += w1[k] * w;
            c2 += w1[64 + k] * w;
            c3 += b1[k] * w;
        }
        sc1[tid] = c1; sc2[tid] = c2; sc3[tid] = c3 + b2[tid];
    }
    int gi = blockIdx.x * 256 + tid;
    if (gi < N) { g_deg[gi] = 1; g_cols[gi * MAXD] = gi; }
    __syncthreads();

    int b = *ts;
    float t = (b > -100000 && b < 100000) ? (float)b : __int_as_float(b);
    int base = blockIdx.x * 4096;
    #pragma unroll
    for (int it = 0; it < 16; it++) {
        int idx = base + it * 256 + tid;
        int i = idx >> 6, c = idx & 63;
        float p = (t - arr[i]) / (dep[i] - arr[i]);
        float v = p * sc1[c] + hard[i] * sc2[c] + sc3[c];
        g_x[idx] = v;
        g_h[idx] = v;
    }
}

// ---------------- k_edges: build in-neighbor lists (float4 streaming, 128 slices) ----------------
__global__ void k_edges(const float* __restrict__ adj) {
    int gid = blockIdx.x * blockDim.x + threadIdx.x;   // 131072 threads
    int i4 = gid & (N / 4 - 1);
    int s = gid >> 10;                                  // 0..127
    const int JS = 32;
    int j0 = s * JS;
    const float4* p = (const float4*)adj + (size_t)j0 * (N / 4) + i4;
    int i = i4 * 4;
    #pragma unroll 4
    for (int jj = 0; jj < JS; jj++) {
        float4 v = __ldcs(p);
        p += N / 4;
        int j = j0 + jj;
        if (v.x != 0.f && j != i) {
            int sl = atomicAdd(&g_deg[i], 1);
            if (sl < MAXD) g_cols[i * MAXD + sl] = j;
        }
        if (v.y != 0.f && j != i + 1) {
            int sl = atomicAdd(&g_deg[i + 1], 1);
            if (sl < MAXD) g_cols[(i + 1) * MAXD + sl] = j;
        }
        if (v.z != 0.f && j != i + 2) {
            int sl = atomicAdd(&g_deg[i + 2], 1);
            if (sl < MAXD) g_cols[(i + 2) * MAXD + sl] = j;
        }
        if (v.w != 0.f && j != i + 3) {
            int sl = atomicAdd(&g_deg[i + 3], 1);
            if (sl < MAXD) g_cols[(i + 3) * MAXD + sl] = j;
        }
    }
}

// ---------------- k_gemm: one warp per row, W in smem, h via shfl, fused scores ----------------
__global__ void k_gemm(const float* __restrict__ W,
                       const float* __restrict__ asrc, const float* __restrict__ adst) {
    __shared__ float sW[64 * 64];       // 16KB
    int tid = threadIdx.x;
    const float4* Wv = (const float4*)W;
    float4* sWv = (float4*)sW;
    #pragma unroll 4
    for (int e = tid; e < 1024; e += 256) sWv[e] = Wv[e];
    __syncthreads();

    int w = tid >> 5, lane = tid & 31;
    int row = blockIdx.x * 8 + w;
    float h0 = g_h[row * 64 + lane];
    float h1 = g_h[row * 64 + 32 + lane];

    float a0 = 0.f, a1 = 0.f;
    const int c2 = lane * 2;
    #pragma unroll
    for (int k = 0; k < 32; k++) {
        float hk = __shfl_sync(0xffffffffu, h0, k);
        float2 wv = *(const float2*)&sW[k * 64 + c2];
        a0 += hk * wv.x; a1 += hk * wv.y;
    }
    #pragma unroll
    for (int k = 0; k < 32; k++) {
        float hk = __shfl_sync(0xffffffffu, h1, k);
        float2 wv = *(const float2*)&sW[(k + 32) * 64 + c2];
        a0 += hk * wv.x; a1 += hk * wv.y;
    }
    *(float2*)&g_hw[row * 64 + c2] = make_float2(a0, a1);

    float2 as = ((const float2*)asrc)[lane];
    float2 ad = ((const float2*)adst)[lane];
    float s = a0 * as.x + a1 * as.y;
    float d = a0 * ad.x + a1 * ad.y;
    #pragma unroll
    for (int o = 16; o; o >>= 1) {
        s += __shfl_xor_sync(0xffffffffu, s, o);
        d += __shfl_xor_sync(0xffffffffu, d, o);
    }
    if (lane == 0) { g_ssrc[row] = s; g_sdst[row] = d; }
}

// ---------------- k_attn: 4 warps per row, two-phase ----------------
// Block: 256 threads = 8 warps = 2 rows x 4 warps. grid = N/2.
__global__ void k_attn(const float* __restrict__ bias, int do_relu) {
    __shared__ int   sj[2][MAXD];
    __shared__ float swt[2][MAXD];
    __shared__ float smax[2][4];
    __shared__ float sden[2][4];
    __shared__ float sacc[2][4][64];

    int tid = threadIdx.x;
    int w = tid >> 5, lane = tid & 31;
    int r = w >> 2;                     // local row 0/1
    int q = w & 3;                      // quarter warp
    int wg_tid = q * 32 + lane;         // 0..127 within row group
    int i = blockIdx.x * 2 + r;

    int d = g_deg[i]; if (d > MAXD) d = MAXD;
    int base = i * MAXD;
    float sd = g_sdst[i];

    // ---- phase A: all 128 row-threads compute one logit each ----
    float e = -1e30f; int j = 0;
    if (wg_tid < d) {
        j = g_cols[base + wg_tid];
        e = g_ssrc[j] + sd;
        e = e > 0.f ? e : NEG * e;
    }
    float mx = e;
    #pragma unroll
    for (int o = 16; o; o >>= 1) mx = fmaxf(mx, __shfl_xor_sync(0xffffffffu, mx, o));
    if (lane == 0) smax[r][q] = mx;
    __syncthreads();
    float m = fmaxf(fmaxf(smax[r][0], smax[r][1]), fmaxf(smax[r][2], smax[r][3]));

    float wgt = (wg_tid < d) ? __expf(e - m) : 0.f;
    if (wg_tid < MAXD) { sj[r][wg_tid] = j; swt[r][wg_tid] = wgt; }
    float den = wgt;
    #pragma unroll
    for (int o = 16; o; o >>= 1) den += __shfl_xor_sync(0xffffffffu, den, o);
    if (lane == 0) sden[r][q] = den;
    __syncthreads();

    // ---- phase B: warp q gathers neighbors t = q, q+4, ... ----
    const int c2 = lane * 2;
    float2 A0 = make_float2(0.f, 0.f), A1 = make_float2(0.f, 0.f);
    int t = q;
    for (; t + 4 < d; t += 8) {
        int j0 = sj[r][t], j1 = sj[r][t + 4];
        float w0 = swt[r][t], w1 = swt[r][t + 4];
        float2 h0 = *(const float2*)&g_hw[j0 * 64 + c2];
        float2 h1 = *(const float2*)&g_hw[j1 * 64 + c2];
        A0.x += w0 * h0.x; A0.y += w0 * h0.y;
        A1.x += w1 * h1.x; A1.y += w1 * h1.y;
    }
    if (t < d) {
        int j0 = sj[r][t];
        float w0 = swt[r][t];
        float2 h0 = *(const float2*)&g_hw[j0 * 64 + c2];
        A0.x += w0 * h0.x; A0.y += w0 * h0.y;
    }
    *(float2*)&sacc[r][q][c2] = make_float2(A0.x + A1.x, A0.y + A1.y);
    __syncthreads();

    // ---- combine: warps with q==0 finalize their row ----
    if (q == 0) {
        float denf = sden[r][0] + sden[r][1] + sden[r][2] + sden[r][3];
        float inv = 1.0f / denf;
        float2 p0 = *(const float2*)&sacc[r][0][c2];
        float2 p1 = *(const float2*)&sacc[r][1][c2];
        float2 p2 = *(const float2*)&sacc[r][2][c2];
        float2 p3 = *(const float2*)&sacc[r][3][c2];
        float o0 = (p0.x + p1.x + p2.x + p3.x) * inv;
        float o1 = (p0.y + p1.y + p2.y + p3.y) * inv;
        float2 bb = ((const float2*)bias)[lane];
        o0 += bb.x; o1 += bb.y;
        if (do_relu) { o0 = fmaxf(o0, 0.f); o1 = fmaxf(o1, 0.f); }
        *(float2*)&g_h[i * 64 + c2] = make_float2(o0, o1);
    }
}

// ---------------- k_final1: residual + layernorm + per-block column partials ----------------
__global__ void k_final1() {
    __shared__ float sn[8 * 64];
    int w = threadIdx.x >> 5, lane = threadIdx.x & 31;
    int i = blockIdx.x * 8 + w;
    float v0 = g_x[i * 64 + lane]      + g_h[i * 64 + lane];
    float v1 = g_x[i * 64 + 32 + lane] + g_h[i * 64 + 32 + lane];
    float s = v0 + v1;
    #pragma unroll
    for (int o = 16; o; o >>= 1) s += __shfl_xor_sync(0xffffffffu, s, o);
    float mu = s * (1.0f / 64.0f);
    float d0 = v0 - mu, d1 = v1 - mu;
    float q = d0 * d0 + d1 * d1;
    #pragma unroll
    for (int o = 16; o; o >>= 1) q += __shfl_xor_sync(0xffffffffu, q, o);
    float r = rsqrtf(q * (1.0f / 64.0f) + EPS);
    sn[w * 64 + lane]      = d0 * r;
    sn[w * 64 + 32 + lane] = d1 * r;
    __syncthreads();
    if (threadIdx.x < 64) {
        float p = 0.f;
        #pragma unroll
        for (int ww = 0; ww < 8; ww++) p += sn[ww * 64 + threadIdx.x];
        g_part[blockIdx.x * 64 + threadIdx.x] = p;
    }
}

// ---------------- k_final2: finish mean-pool, value head ----------------
__global__ void k_final2(const float* __restrict__ vw, const float* __restrict__ vb,
                         float* __restrict__ out) {
    __shared__ float sm[256];
    int c = threadIdx.x & 63, g = threadIdx.x >> 6;
    float s = 0.f;
    for (int b = g; b < FIN_BLOCKS; b += 4) s += g_part[b * 64 + c];
    sm[threadIdx.x] = s;
    __syncthreads();
    if (threadIdx.x < 64) {
        float pooled = (sm[c] + sm[64 + c] + sm[128 + c] + sm[192 + c]) * (1.0f / (float)N);
        sm[c] = pooled * vw[c];
    }
    __syncthreads();
    if (threadIdx.x < 32) {
        float t = sm[threadIdx.x] + sm[threadIdx.x + 32];
        #pragma unroll
        for (int o = 16; o; o >>= 1) t += __shfl_xor_sync(0xffffffffu, t, o);
        if (threadIdx.x == 0) {
            float r = t + vb[0];
            out[0] = r > 0.f ? r : 0.f;
        }
    }
}

// ---------------- host ----------------
extern "C" void kernel_launch(void* const* d_in, const int* in_sizes, int n_in,
                              void* d_out, int out_size) {
    const float* adj      = (const float*)d_in[0];
    const int*   ts       = (const int*)  d_in[1];
    const float* arrivals = (const float*)d_in[2];
    const float* depart   = (const float*)d_in[3];
    const float* hard     = (const float*)d_in[4];
    const float* emb_w1   = (const float*)d_in[6];
    const float* emb_b1   = (const float*)d_in[7];
    const float* emb_w2   = (const float*)d_in[8];
    const float* emb_b2   = (const float*)d_in[9];
    const float* gat_w    = (const float*)d_in[10];
    const float* gat_asrc = (const float*)d_in[11];
    const float* gat_adst = (const float*)d_in[12];
    const float* gat_b    = (const float*)d_in[13];
    const float* val_w    = (const float*)d_in[14];
    const float* val_b    = (const float*)d_in[15];

    k_embed<<<64, 256>>>(ts, arrivals, depart, hard, emb_w1, emb_b1, emb_w2, emb_b2);
    k_edges<<<512, 256>>>(adj);

    for (int l = 0; l < NLAYER; l++) {
        k_gemm<<<N / 8, 256>>>(gat_w + l * H * H, gat_asrc + l * H, gat_adst + l * H);
        k_attn<<<N / 2, 256>>>(gat_b + l * H, (l < NLAYER - 1) ? 1 : 0);
    }

    k_final1<<<FIN_BLOCKS, 256>>>();
    k_final2<<<1, 256>>>(val_w, val_b, (float*)d_out);
}